// round 15
// baseline (speedup 1.0000x reference)
#include <cuda_runtime.h>
#include <cuda_bf16.h>
#include <cstdint>

#define D       512
#define HEADS   8
#define DH      64
#define NB      4
#define TQ      512
#define TS      512
#define VOCABSZ 32000
#define ROWS    (NB*TQ)          // 2048
#define NBMPW   (VOCABSZ/32)     // 1000 bitmap words per batch

typedef unsigned long long ull;

// ---------------- scratch ----------------
__device__ float g_bc[D];
__device__ __nv_bfloat16 g_WcB[D*D];
__device__ __nv_bfloat16 g_WkB[D*D];
__device__ __nv_bfloat16 g_QKB[2*ROWS*D];           // Q' rows [0,2048), K rows [2048,4096)
__device__ __nv_bfloat16 g_scoresB[NB*HEADS*TQ*TS]; // 16.8 MB
__device__ int   g_gid[NB*TS];
__device__ int   g_ng[NB];
__device__ int   g_tokmap[NB*VOCABSZ];
__device__ unsigned g_bmp[NB*NBMPW];

// ---------------- f32x2 helpers ----------------
__device__ __forceinline__ ull pack2s(float x){
    ull r; asm("mov.b64 %0, {%1, %1};" : "=l"(r) : "r"(__float_as_uint(x))); return r;
}
__device__ __forceinline__ ull pack2f(float x, float y){
    ull r; asm("mov.b64 %0, {%1, %2};" : "=l"(r) : "r"(__float_as_uint(x)), "r"(__float_as_uint(y))); return r;
}
__device__ __forceinline__ void ffma2(ull& d, ull a, ull b){
    asm("fma.rn.f32x2 %0, %1, %2, %0;" : "+l"(d) : "l"(a), "l"(b));
}
__device__ __forceinline__ float2 unpack2(ull v){
    unsigned lo, hi; asm("mov.b64 {%0, %1}, %2;" : "=r"(lo), "=r"(hi) : "l"(v));
    return make_float2(__uint_as_float(lo), __uint_as_float(hi));
}

// ---------------- HMMA / cp.async helpers ----------------
__device__ __forceinline__ uint32_t smem_u32(const void* p){
    uint32_t a;
    asm("{ .reg .u64 t; cvta.to.shared.u64 t, %1; cvt.u32.u64 %0, t; }" : "=r"(a) : "l"(p));
    return a;
}
__device__ __forceinline__ void ldm_x4(uint32_t addr, uint32_t& r0, uint32_t& r1,
                                       uint32_t& r2, uint32_t& r3){
    asm volatile("ldmatrix.sync.aligned.m8n8.x4.shared.b16 {%0,%1,%2,%3}, [%4];"
        : "=r"(r0), "=r"(r1), "=r"(r2), "=r"(r3) : "r"(addr));
}
__device__ __forceinline__ void mma_bf16(float* c, uint32_t a0, uint32_t a1, uint32_t a2,
                                         uint32_t a3, uint32_t b0, uint32_t b1){
    asm volatile("mma.sync.aligned.m16n8k16.row.col.f32.bf16.bf16.f32 "
        "{%0,%1,%2,%3}, {%4,%5,%6,%7}, {%8,%9}, {%0,%1,%2,%3};"
        : "+f"(c[0]), "+f"(c[1]), "+f"(c[2]), "+f"(c[3])
        : "r"(a0), "r"(a1), "r"(a2), "r"(a3), "r"(b0), "r"(b1));
}
__device__ __forceinline__ void cp16(uint32_t dst, const void* src){
    asm volatile("cp.async.cg.shared.global [%0], [%1], 16;" :: "r"(dst), "l"(src));
}
#define CP_COMMIT() asm volatile("cp.async.commit_group;" ::: "memory")
#define CP_WAIT(n)  asm volatile("cp.async.wait_group %0;" :: "n"(n) : "memory")

// ---- 128xBN-tile NT GEMM on HMMA (bf16 A+B), cp.async double-buffered ----
template<int NCHUNK, int BN, bool OUT_BF16, bool BIAS>
__device__ __forceinline__ void hgemm_nt(
    const __nv_bfloat16* __restrict__ A, const __nv_bfloat16* __restrict__ B,
    void* __restrict__ Cout, int ldc, const float* __restrict__ bias,
    float alpha, int m0, int n0)
{
    constexpr int ABYTES = 128*128;
    constexpr int BBYTES = BN*128;
    constexpr int BUF = ABYTES + BBYTES;
    constexpr int FM = (BN == 128) ? 4 : 2;
    constexpr int WN = (BN == 128) ? 4 : 2;

    __shared__ __align__(16) uint8_t sm[2*BUF];
    const int tid = threadIdx.x;
    const int w = tid >> 5, lane = tid & 31;
    const int wm = w / WN, wn = w % WN;
    const int mbase = wm * (FM*16);
    const uint32_t sbase = smem_u32(sm);

    float acc[FM][4][4];
#pragma unroll
    for (int i=0;i<FM;i++)
#pragma unroll
        for (int j=0;j<4;j++)
#pragma unroll
            for (int k=0;k<4;k++) acc[i][j][k] = 0.f;

    auto issue = [&](int c, int bsel){
        const uint32_t dstA = sbase + bsel*BUF;
        const uint32_t dstB = dstA + ABYTES;
#pragma unroll
        for (int it = 0; it < 4; it++){
            const int i = tid + it*256;
            const int r = i >> 3, cb = i & 7;
            const int sw = (cb ^ (r & 7)) << 4;
            cp16(dstA + r*128 + sw, A + (size_t)(m0 + r)*512 + c*64 + cb*8);
        }
#pragma unroll
        for (int it = 0; it < BN/32; it++){
            const int i = tid + it*256;
            const int r = i >> 3, cb = i & 7;
            const int sw = (cb ^ (r & 7)) << 4;
            cp16(dstB + r*128 + sw, B + (size_t)(n0 + r)*512 + c*64 + cb*8);
        }
        CP_COMMIT();
    };

    issue(0, 0);
    if (NCHUNK > 1) issue(1, 1);

    const int rowA_l = (lane & 7) + ((lane >> 3) & 1) * 8;
    const int kbA_l  = lane >> 4;
    const int rowB_l = (lane & 7) + ((lane >> 4) & 1) * 8;
    const int kbB_l  = (lane >> 3) & 1;

#pragma unroll
    for (int c = 0; c < NCHUNK; c++){
        if (c + 1 < NCHUNK) { CP_WAIT(1); } else { CP_WAIT(0); }
        __syncthreads();
        const uint32_t sA = sbase + (c & 1)*BUF;
        const uint32_t sB = sA + ABYTES;
#pragma unroll
        for (int ks = 0; ks < 4; ks++){
            uint32_t af[FM][4];
#pragma unroll
            for (int fm = 0; fm < FM; fm++){
                const int row = mbase + fm*16 + rowA_l;
                const int kb  = ks*2 + kbA_l;
                ldm_x4(sA + row*128 + ((kb ^ (row & 7)) << 4),
                       af[fm][0], af[fm][1], af[fm][2], af[fm][3]);
            }
            uint32_t bf[2][4];
#pragma unroll
            for (int fn = 0; fn < 2; fn++){
                const int row = wn*32 + fn*16 + rowB_l;
                const int kb  = ks*2 + kbB_l;
                ldm_x4(sB + row*128 + ((kb ^ (row & 7)) << 4),
                       bf[fn][0], bf[fn][1], bf[fn][2], bf[fn][3]);
            }
#pragma unroll
            for (int fm = 0; fm < FM; fm++)
#pragma unroll
                for (int j = 0; j < 4; j++)
                    mma_bf16(acc[fm][j], af[fm][0], af[fm][1], af[fm][2], af[fm][3],
                             bf[j>>1][(j&1)*2], bf[j>>1][(j&1)*2 + 1]);
        }
        __syncthreads();
        if (c + 2 < NCHUNK) issue(c + 2, c & 1);
    }

    const int r_l = lane >> 2, c_l = (lane & 3) * 2;
#pragma unroll
    for (int fm = 0; fm < FM; fm++){
#pragma unroll
        for (int j = 0; j < 4; j++){
            const int row = m0 + mbase + fm*16 + r_l;
            const int col = n0 + wn*32 + (j>>1)*16 + (j&1)*8 + c_l;
            const float* a = acc[fm][j];
            float b0 = 0.f, b1 = 0.f;
            if (BIAS){ b0 = bias[col]; b1 = bias[col+1]; }
            if (OUT_BF16){
                __nv_bfloat16* O = (__nv_bfloat16*)Cout;
                *(__nv_bfloat162*)(O + (size_t)row*ldc + col) =
                    __floats2bfloat162_rn((a[0]+b0)*alpha, (a[1]+b1)*alpha);
                *(__nv_bfloat162*)(O + (size_t)(row+8)*ldc + col) =
                    __floats2bfloat162_rn((a[2]+b0)*alpha, (a[3]+b1)*alpha);
            } else {
                float* O = (float*)Cout;
                *(float2*)(O + (size_t)row*ldc + col) = make_float2((a[0]+b0)*alpha, (a[1]+b1)*alpha);
                *(float2*)(O + (size_t)(row+8)*ldc + col) = make_float2((a[2]+b0)*alpha, (a[3]+b1)*alpha);
            }
        }
    }
}

// ---- proj GEMM: A fp32 (LDG + register convert), B bf16 via cp.async. ----
// 128x64 tile, 256 threads, K=512 (8 chunks). C bf16 = (A.B^T + bias)*alpha.
__device__ __forceinline__ void hgemm_a32(
    const float* __restrict__ A, const __nv_bfloat16* __restrict__ B,
    __nv_bfloat16* __restrict__ C, const float* __restrict__ bias,
    float alpha, int m0, int n0)
{
    constexpr int ABYTES = 128*128;   // bf16 A region
    constexpr int BBYTES = 64*128;
    constexpr int BUF = ABYTES + BBYTES;   // 24576
    __shared__ __align__(16) uint8_t sm[2*BUF];   // 48 KB
    const int tid = threadIdx.x;
    const int w = tid >> 5, lane = tid & 31;
    const int wm = w >> 1, wn = w & 1;            // 4 x 2 warps
    const int mbase = wm * 32;
    const uint32_t sbase = smem_u32(sm);

    float acc[2][4][4];
#pragma unroll
    for (int i=0;i<2;i++)
#pragma unroll
        for (int j=0;j<4;j++)
#pragma unroll
            for (int k=0;k<4;k++) acc[i][j][k] = 0.f;

    float4 rA[8];
    auto ldA = [&](int c){
#pragma unroll
        for (int it = 0; it < 4; it++){
            const int i = tid + it*256;
            const int r = i >> 3, cb = i & 7;
            const float* p = A + (size_t)(m0 + r)*512 + c*64 + cb*8;
            rA[2*it]   = *(const float4*)p;
            rA[2*it+1] = *(const float4*)(p + 4);
        }
    };
    auto stsA = [&](int bsel){
        uint8_t* dst = sm + bsel*BUF;
#pragma unroll
        for (int it = 0; it < 4; it++){
            const int i = tid + it*256;
            const int r = i >> 3, cb = i & 7;
            const int sw = (cb ^ (r & 7)) << 4;
            __nv_bfloat162 b0 = __floats2bfloat162_rn(rA[2*it].x,   rA[2*it].y);
            __nv_bfloat162 b1 = __floats2bfloat162_rn(rA[2*it].z,   rA[2*it].w);
            __nv_bfloat162 b2 = __floats2bfloat162_rn(rA[2*it+1].x, rA[2*it+1].y);
            __nv_bfloat162 b3 = __floats2bfloat162_rn(rA[2*it+1].z, rA[2*it+1].w);
            uint4 v;
            v.x = *(uint32_t*)&b0; v.y = *(uint32_t*)&b1;
            v.z = *(uint32_t*)&b2; v.w = *(uint32_t*)&b3;
            *(uint4*)(dst + r*128 + sw) = v;
        }
    };
    auto cpB = [&](int c, int bsel){
        const uint32_t dstB = sbase + bsel*BUF + ABYTES;
#pragma unroll
        for (int it = 0; it < 2; it++){
            const int i = tid + it*256;
            const int r = i >> 3, cb = i & 7;
            const int sw = (cb ^ (r & 7)) << 4;
            cp16(dstB + r*128 + sw, B + (size_t)(n0 + r)*512 + c*64 + cb*8);
        }
        CP_COMMIT();
    };

    // prologue
    ldA(0); stsA(0);
    cpB(0, 0);
    ldA(1);
    cpB(1, 1);

    const int rowA_l = (lane & 7) + ((lane >> 3) & 1) * 8;
    const int kbA_l  = lane >> 4;
    const int rowB_l = (lane & 7) + ((lane >> 4) & 1) * 8;
    const int kbB_l  = (lane >> 3) & 1;

#pragma unroll
    for (int c = 0; c < 8; c++){
        if (c + 1 < 8) { CP_WAIT(1); } else { CP_WAIT(0); }
        __syncthreads();
        if (c + 1 < 8) stsA((c + 1) & 1);       // A of next chunk -> free buffer
        const uint32_t sA = sbase + (c & 1)*BUF;
        const uint32_t sB = sA + ABYTES;
#pragma unroll
        for (int ks = 0; ks < 4; ks++){
            uint32_t af[2][4];
#pragma unroll
            for (int fm = 0; fm < 2; fm++){
                const int row = mbase + fm*16 + rowA_l;
                const int kb  = ks*2 + kbA_l;
                ldm_x4(sA + row*128 + ((kb ^ (row & 7)) << 4),
                       af[fm][0], af[fm][1], af[fm][2], af[fm][3]);
            }
            uint32_t bf[2][4];
#pragma unroll
            for (int fn = 0; fn < 2; fn++){
                const int row = wn*32 + fn*16 + rowB_l;
                const int kb  = ks*2 + kbB_l;
                ldm_x4(sB + row*128 + ((kb ^ (row & 7)) << 4),
                       bf[fn][0], bf[fn][1], bf[fn][2], bf[fn][3]);
            }
#pragma unroll
            for (int fm = 0; fm < 2; fm++)
#pragma unroll
                for (int j = 0; j < 4; j++)
                    mma_bf16(acc[fm][j], af[fm][0], af[fm][1], af[fm][2], af[fm][3],
                             bf[j>>1][(j&1)*2], bf[j>>1][(j&1)*2 + 1]);
        }
        __syncthreads();
        if (c + 2 < 8){ ldA(c + 2); cpB(c + 2, c & 1); }
    }

    const int r_l = lane >> 2, c_l = (lane & 3) * 2;
#pragma unroll
    for (int fm = 0; fm < 2; fm++){
#pragma unroll
        for (int j = 0; j < 4; j++){
            const int row = m0 + mbase + fm*16 + r_l;
            const int col = n0 + wn*32 + (j>>1)*16 + (j&1)*8 + c_l;
            const float* a = acc[fm][j];
            const float b0 = bias[col], b1 = bias[col+1];
            *(__nv_bfloat162*)(C + (size_t)row*512 + col) =
                __floats2bfloat162_rn((a[0]+b0)*alpha, (a[1]+b1)*alpha);
            *(__nv_bfloat162*)(C + (size_t)(row+8)*512 + col) =
                __floats2bfloat162_rn((a[2]+b0)*alpha, (a[3]+b1)*alpha);
        }
    }
}

// proj: 128x64 tiles, grid (8,16,2) = 256 CTAs; A fp32 direct
__global__ void __launch_bounds__(256) k_proj_h(
    const float* __restrict__ dec, const float* __restrict__ enc,
    const float* __restrict__ bk){
    if (blockIdx.z == 0)
        hgemm_a32(dec, g_WcB, g_QKB, g_bc, 0.125f, blockIdx.y*128, blockIdx.x*64);
    else
        hgemm_a32(enc, g_WkB, g_QKB + (size_t)ROWS*D, bk, 1.0f, blockIdx.y*128, blockIdx.x*64);
}

// scores: 128x128 tiles, grid (4,4,32)
__global__ void __launch_bounds__(256) k_scores_h(){
    const int z = blockIdx.z, b = z >> 3, h = z & 7;
    hgemm_nt<1,128,true,false>(g_QKB + (size_t)(b*TQ)*D + h*DH,
                               g_QKB + (size_t)(ROWS + b*TS)*D + h*DH,
                               g_scoresB + (size_t)z*TQ*TS, TS, nullptr, 1.0f,
                               blockIdx.y*128, blockIdx.x*128);
}

// ---------------- merged prep kernel ----------------
// blocks [0,4): grouping ; [4,20): bc ; [20,276): fold ; [276,532): Wk fp32->bf16
#define PREP_GRP_END 4
#define PREP_BC_END  20
#define PREP_FOLD_END 276
#define PREP_TOTAL   (PREP_FOLD_END + 256)    // 532

__global__ void k_prep(const int* __restrict__ src,
                       const float* __restrict__ Wq, const float* __restrict__ bfcQ,
                       const float* __restrict__ bq, const float* __restrict__ WfcQ,
                       const float* __restrict__ Wk){
    __shared__ __align__(16) int shraw[4656];   // 18.6 KB
    const int blk = blockIdx.x, t = threadIdx.x;
    const int lane = t & 31, w = t >> 5;

    if (blk < PREP_GRP_END){
        const int b = blk;
        int* stok   = shraw;            // 512
        int* sfirst = shraw + 512;      // 512
        int* sgarr  = shraw + 1024;     // 512
        int* hkey   = shraw + 1536;     // 1024
        int* hval   = shraw + 2560;     // 1024
        unsigned* sbmp = (unsigned*)(shraw + 3584); // 1000
        int* swcnt  = shraw + 4584;     // 16
        int* swbase = shraw + 4600;     // 16

        stok[t]     = src[b*TS + t];
        stok[t+256] = src[b*TS + t + 256];
        for (int i = t; i < 1024; i += 256){ hkey[i] = -1; hval[i] = 0x7fffffff; }
        for (int i = t; i < NBMPW; i += 256) sbmp[i] = 0u;
        __syncthreads();

#pragma unroll
        for (int half = 0; half < 2; half++){
            const int jj = t + half*256;
            const int tok = stok[jj];
            int slot = (int)(((unsigned)tok * 2654435761u) >> 22);
            while (true){
                int k = atomicCAS(&hkey[slot], -1, tok);
                if (k == -1 || k == tok) break;
                slot = (slot + 1) & 1023;
            }
            atomicMin(&hval[slot], jj);
            sfirst[jj] = slot;
        }
        __syncthreads();
        const int f0 = hval[sfirst[t]];
        const int f1 = hval[sfirst[t+256]];
        sfirst[t] = f0; sfirst[t+256] = f1;

        const unsigned ltm = (1u << lane) - 1u;
        const unsigned m0 = __ballot_sync(0xFFFFFFFFu, f0 == t);
        const unsigned m1 = __ballot_sync(0xFFFFFFFFu, f1 == t + 256);
        if (lane == 0){ swcnt[w] = __popc(m0); swcnt[8 + w] = __popc(m1); }
        __syncthreads();
        if (t == 0){
            int run = 0;
#pragma unroll
            for (int i = 0; i < 16; i++){ swbase[i] = run; run += swcnt[i]; }
            g_ng[b] = run;
        }
        __syncthreads();
        sgarr[t]       = swbase[w]     + __popc(m0 & ltm);
        sgarr[t + 256] = swbase[8 + w] + __popc(m1 & ltm);
        __syncthreads();

#pragma unroll
        for (int half = 0; half < 2; half++){
            const int jj = t + half*256;
            const int f = sfirst[jj];
            const int g = sgarr[f];
            g_gid[b*TS + jj] = g;
            if (f == jj){
                const int tok = stok[jj];
                g_tokmap[b*VOCABSZ + tok] = g;
                atomicOr(&sbmp[tok >> 5], 1u << (tok & 31));
            }
        }
        __syncthreads();
        for (int i = t; i < NBMPW; i += 256) g_bmp[b*NBMPW + i] = sbmp[i];
    } else if (blk < PREP_BC_END){
        const int row = (blk - PREP_GRP_END)*32 + (t >> 3);
        const int l8 = t & 7;
        float s = 0.f;
        for (int k = l8; k < D; k += 8) s += Wq[(size_t)row*D + k] * bfcQ[k];
        s += __shfl_down_sync(0xFFFFFFFFu, s, 4, 8);
        s += __shfl_down_sync(0xFFFFFFFFu, s, 2, 8);
        s += __shfl_down_sync(0xFFFFFFFFu, s, 1, 8);
        if (l8 == 0) g_bc[row] = s + bq[row];
    } else if (blk < PREP_FOLD_END){
        const int idx = blk - PREP_BC_END;
        const int m0 = (idx >> 4)*32, n0 = (idx & 15)*32;
        float (*As)[34] = (float(*)[34])shraw;
        float (*Bs)[34] = (float(*)[34])((char*)shraw + 4352);
        const int tx = t & 15, ty = t >> 4;
        ull acc0 = 0ULL, acc1 = 0ULL;
        const int lrow = t >> 3, lc4 = t & 7;
        for (int c0 = 0; c0 < D; c0 += 32){
            float4 av = *(const float4*)(Wq   + (size_t)(m0 + lrow)*D + c0 + lc4*4);
            float4 bv = *(const float4*)(WfcQ + (size_t)(c0 + lrow)*D + n0 + lc4*4);
            __syncthreads();
            const int kb = lc4*4;
            As[kb+0][lrow]=av.x; As[kb+1][lrow]=av.y; As[kb+2][lrow]=av.z; As[kb+3][lrow]=av.w;
            Bs[lrow][kb+0]=bv.x; Bs[lrow][kb+1]=bv.y; Bs[lrow][kb+2]=bv.z; Bs[lrow][kb+3]=bv.w;
            __syncthreads();
#pragma unroll
            for (int kk = 0; kk < 32; kk++){
                float2 a = *(const float2*)&As[kk][ty*2];
                float2 b = *(const float2*)&Bs[kk][tx*2];
                ull ap = pack2f(a.x, a.y);
                ffma2(acc0, ap, pack2s(b.x));
                ffma2(acc1, ap, pack2s(b.y));
            }
        }
        float2 u0 = unpack2(acc0), u1 = unpack2(acc1);
        const int r0 = m0 + ty*2, cc = n0 + tx*2;
        *(__nv_bfloat162*)(g_WcB + (size_t)r0*D + cc)     = __floats2bfloat162_rn(u0.x, u1.x);
        *(__nv_bfloat162*)(g_WcB + (size_t)(r0+1)*D + cc) = __floats2bfloat162_rn(u0.y, u1.y);
    } else {
        // Wk fp32 -> bf16 (262144 elements, 256 blocks)
        const int i4 = ((blk - PREP_FOLD_END)*256 + t) * 4;
        float4 v = *(const float4*)(Wk + i4);
        __nv_bfloat16* d = g_WkB + i4;
        *(__nv_bfloat162*)d       = __floats2bfloat162_rn(v.x, v.y);
        *(__nv_bfloat162*)(d + 2) = __floats2bfloat162_rn(v.z, v.w);
    }
}

// ---------------- fused attention-combine + output stream (R12 version) ----------------
// grid 2048 (b,q), 512 threads = 16 warps.
__global__ void __launch_bounds__(512) k_attn_final(
    const float* __restrict__ dec, const float* __restrict__ Wfcw,
    const float* __restrict__ bfcw, const float* __restrict__ p1,
    float* __restrict__ out){
    const int bq = blockIdx.x, b = bq >> 9, q = bq & 511;
    const int t = threadIdx.x, lane = t & 31, w = t >> 5;
    __shared__ float sattn[HEADS][512];
    __shared__ float gsum[512];
    __shared__ float sinv[HEADS];
    __shared__ float sredg[8];
    __shared__ float sredz[16];
    __shared__ unsigned sbmp[NBMPW];
    gsum[t] = 0.f;

    if (w < 8){
        const int h = w;
        const uint2* rp = (const uint2*)(g_scoresB + ((size_t)(b*HEADS + h)*TQ + q) * TS);
        float4 ev[4];
        float m = -1e30f;
#pragma unroll
        for (int j = 0; j < 4; j++){
            const uint2 u = rp[lane + 32*j];
            const __nv_bfloat162 p0 = *(const __nv_bfloat162*)&u.x;
            const __nv_bfloat162 pq = *(const __nv_bfloat162*)&u.y;
            float4 v = make_float4(__bfloat162float(p0.x), __bfloat162float(p0.y),
                                   __bfloat162float(pq.x), __bfloat162float(pq.y));
            ev[j] = v;
            m = fmaxf(m, fmaxf(fmaxf(v.x, v.y), fmaxf(v.z, v.w)));
        }
#pragma unroll
        for (int o = 16; o > 0; o >>= 1) m = fmaxf(m, __shfl_xor_sync(0xFFFFFFFFu, m, o));
        float s = 0.f;
#pragma unroll
        for (int j = 0; j < 4; j++){
            ev[j].x = __expf(ev[j].x - m); ev[j].y = __expf(ev[j].y - m);
            ev[j].z = __expf(ev[j].z - m); ev[j].w = __expf(ev[j].w - m);
            s += ev[j].x + ev[j].y + ev[j].z + ev[j].w;
        }
#pragma unroll
        for (int o = 16; o > 0; o >>= 1) s += __shfl_xor_sync(0xFFFFFFFFu, s, o);
        if (lane == 0) sinv[h] = 1.0f / (8.0f * s);
#pragma unroll
        for (int j = 0; j < 4; j++)
            *(float4*)&sattn[h][(lane + 32*j)*4] = ev[j];
    } else {
        const int t2 = t - 256;
        for (int i = t2; i < NBMPW; i += 256) sbmp[i] = g_bmp[b*NBMPW + i];
        const float* drow = dec + (size_t)bq * D;
        float pw = drow[t2]*Wfcw[t2] + drow[t2+256]*Wfcw[t2+256];
#pragma unroll
        for (int o = 16; o > 0; o >>= 1) pw += __shfl_xor_sync(0xFFFFFFFFu, pw, o);
        if (lane == 0) sredg[w - 8] = pw;
    }
    __syncthreads();

    {
        float a = 0.f;
#pragma unroll
        for (int hh = 0; hh < HEADS; hh++) a += sattn[hh][t] * sinv[hh];
        atomicAdd(&gsum[g_gid[b*TS + t]], a);
    }
    __syncthreads();

    float wsum = sredg[0];
#pragma unroll
    for (int i = 1; i < 8; i++) wsum += sredg[i];
    const float wgate = 1.0f / (1.0f + __expf(-(wsum + bfcw[0])));

    const int G = g_ng[b];
    float pz = 0.f;
    if (t < G){ float e = __expf(gsum[t]); gsum[t] = e; pz += e; }
#pragma unroll
    for (int o = 16; o > 0; o >>= 1) pz += __shfl_xor_sync(0xFFFFFFFFu, pz, o);
    if (lane == 0) sredz[w] = pz;
    __syncthreads();
    float zs = sredz[0];
#pragma unroll
    for (int i = 1; i < 16; i++) zs += sredz[i];
    const float Z = (float)(VOCABSZ - G) + zs;
    const float wz = wgate / Z;
    const float cw = 1.0f - wgate;

    const float4* p14 = (const float4*)(p1 + (size_t)bq * VOCABSZ);
    float4* o4 = (float4*)(out + (size_t)bq * VOCABSZ);
    const int* tmap = g_tokmap + (size_t)b * VOCABSZ;

#pragma unroll 4
    for (int i = t; i < VOCABSZ/4; i += 512){
        float4 v = __ldcs(&p14[i]);
        unsigned bits = (sbmp[i >> 3] >> ((i & 7) * 4)) & 0xFu;
        float4 r;
        r.x = fmaf(cw, v.x, wz); r.y = fmaf(cw, v.y, wz);
        r.z = fmaf(cw, v.z, wz); r.w = fmaf(cw, v.w, wz);
        if (bits){
            const int v0 = i * 4;
            if (bits & 1u) r.x = wz * gsum[tmap[v0+0]] + cw*v.x;
            if (bits & 2u) r.y = wz * gsum[tmap[v0+1]] + cw*v.y;
            if (bits & 4u) r.z = wz * gsum[tmap[v0+2]] + cw*v.z;
            if (bits & 8u) r.w = wz * gsum[tmap[v0+3]] + cw*v.w;
        }
        __stcs(&o4[i], r);
    }
}

// ---------------- launch ----------------
extern "C" void kernel_launch(void* const* d_in, const int* in_sizes, int n_in,
                              void* d_out, int out_size){
    int off = (in_sizes[0] == 1) ? 1 : 0;
    const float* dec  = (const float*)d_in[off + 0];
    const float* enc  = (const float*)d_in[off + 1];
    const int*   src  = (const int*)  d_in[off + 2];
    const float* p1   = (const float*)d_in[off + 3];
    const float* WfcQ = (const float*)d_in[off + 4];
    const float* bfcQ = (const float*)d_in[off + 5];
    const float* Wq   = (const float*)d_in[off + 6];
    const float* bq   = (const float*)d_in[off + 7];
    const float* Wk   = (const float*)d_in[off + 8];
    const float* bk   = (const float*)d_in[off + 9];
    const float* Wfcw = (const float*)d_in[off + 10];
    const float* bfcw = (const float*)d_in[off + 11];
    float* out = (float*)d_out;

    k_prep      <<<PREP_TOTAL, 256>>>(src, Wq, bfcQ, bq, WfcQ, Wk);
    k_proj_h    <<<dim3(8,16,2), 256>>>(dec, enc, bk);
    k_scores_h  <<<dim3(4,4,32), 256>>>();
    k_attn_final<<<ROWS, 512>>>(dec, Wfcw, bfcw, p1, out);
}

// round 16
// speedup vs baseline: 1.0935x; 1.0935x over previous
#include <cuda_runtime.h>
#include <cuda_bf16.h>
#include <cstdint>

#define D       512
#define HEADS   8
#define DH      64
#define NB      4
#define TQ      512
#define TS      512
#define VOCABSZ 32000
#define ROWS    (NB*TQ)          // 2048
#define NBMPW   (VOCABSZ/32)     // 1000 bitmap words per batch

// ---------------- scratch ----------------
__device__ __nv_bfloat16 g_WkB[D*D];
__device__ __nv_bfloat16 g_WqB[D*D];
__device__ __nv_bfloat16 g_WfcQB[D*D];
__device__ __nv_bfloat16 g_decB[ROWS*D];
__device__ __nv_bfloat16 g_encB[ROWS*D];
__device__ __nv_bfloat16 g_CQB[ROWS*D];             // copy-query intermediate
__device__ __nv_bfloat16 g_QKB[2*ROWS*D];           // Q' rows [0,2048), K rows [2048,4096)
__device__ __nv_bfloat16 g_scoresB[NB*HEADS*TQ*TS]; // 16.8 MB
__device__ int   g_gid[NB*TS];
__device__ int   g_ng[NB];
__device__ int   g_tokmap[NB*VOCABSZ];
__device__ unsigned g_bmp[NB*NBMPW];

// ---------------- HMMA / cp.async helpers ----------------
__device__ __forceinline__ uint32_t smem_u32(const void* p){
    uint32_t a;
    asm("{ .reg .u64 t; cvta.to.shared.u64 t, %1; cvt.u32.u64 %0, t; }" : "=r"(a) : "l"(p));
    return a;
}
__device__ __forceinline__ void ldm_x4(uint32_t addr, uint32_t& r0, uint32_t& r1,
                                       uint32_t& r2, uint32_t& r3){
    asm volatile("ldmatrix.sync.aligned.m8n8.x4.shared.b16 {%0,%1,%2,%3}, [%4];"
        : "=r"(r0), "=r"(r1), "=r"(r2), "=r"(r3) : "r"(addr));
}
__device__ __forceinline__ void mma_bf16(float* c, uint32_t a0, uint32_t a1, uint32_t a2,
                                         uint32_t a3, uint32_t b0, uint32_t b1){
    asm volatile("mma.sync.aligned.m16n8k16.row.col.f32.bf16.bf16.f32 "
        "{%0,%1,%2,%3}, {%4,%5,%6,%7}, {%8,%9}, {%0,%1,%2,%3};"
        : "+f"(c[0]), "+f"(c[1]), "+f"(c[2]), "+f"(c[3])
        : "r"(a0), "r"(a1), "r"(a2), "r"(a3), "r"(b0), "r"(b1));
}
__device__ __forceinline__ void cp16(uint32_t dst, const void* src){
    asm volatile("cp.async.cg.shared.global [%0], [%1], 16;" :: "r"(dst), "l"(src));
}
#define CP_COMMIT() asm volatile("cp.async.commit_group;" ::: "memory")
#define CP_WAIT(n)  asm volatile("cp.async.wait_group %0;" :: "n"(n) : "memory")

// ---- 128xBN-tile NT GEMM on HMMA (bf16 A+B), cp.async double-buffered ----
template<int NCHUNK, int BN, bool OUT_BF16, bool BIAS>
__device__ __forceinline__ void hgemm_nt(
    const __nv_bfloat16* __restrict__ A, const __nv_bfloat16* __restrict__ B,
    void* __restrict__ Cout, int ldc, const float* __restrict__ bias,
    float alpha, int m0, int n0)
{
    constexpr int ABYTES = 128*128;
    constexpr int BBYTES = BN*128;
    constexpr int BUF = ABYTES + BBYTES;
    constexpr int FM = (BN == 128) ? 4 : 2;
    constexpr int WN = (BN == 128) ? 4 : 2;

    __shared__ __align__(16) uint8_t sm[2*BUF];
    const int tid = threadIdx.x;
    const int w = tid >> 5, lane = tid & 31;
    const int wm = w / WN, wn = w % WN;
    const int mbase = wm * (FM*16);
    const uint32_t sbase = smem_u32(sm);

    float acc[FM][4][4];
#pragma unroll
    for (int i=0;i<FM;i++)
#pragma unroll
        for (int j=0;j<4;j++)
#pragma unroll
            for (int k=0;k<4;k++) acc[i][j][k] = 0.f;

    auto issue = [&](int c, int bsel){
        const uint32_t dstA = sbase + bsel*BUF;
        const uint32_t dstB = dstA + ABYTES;
#pragma unroll
        for (int it = 0; it < 4; it++){
            const int i = tid + it*256;
            const int r = i >> 3, cb = i & 7;
            const int sw = (cb ^ (r & 7)) << 4;
            cp16(dstA + r*128 + sw, A + (size_t)(m0 + r)*512 + c*64 + cb*8);
        }
#pragma unroll
        for (int it = 0; it < BN/32; it++){
            const int i = tid + it*256;
            const int r = i >> 3, cb = i & 7;
            const int sw = (cb ^ (r & 7)) << 4;
            cp16(dstB + r*128 + sw, B + (size_t)(n0 + r)*512 + c*64 + cb*8);
        }
        CP_COMMIT();
    };

    issue(0, 0);
    if (NCHUNK > 1) issue(1, 1);

    const int rowA_l = (lane & 7) + ((lane >> 3) & 1) * 8;
    const int kbA_l  = lane >> 4;
    const int rowB_l = (lane & 7) + ((lane >> 4) & 1) * 8;
    const int kbB_l  = (lane >> 3) & 1;

#pragma unroll
    for (int c = 0; c < NCHUNK; c++){
        if (c + 1 < NCHUNK) { CP_WAIT(1); } else { CP_WAIT(0); }
        __syncthreads();
        const uint32_t sA = sbase + (c & 1)*BUF;
        const uint32_t sB = sA + ABYTES;
#pragma unroll
        for (int ks = 0; ks < 4; ks++){
            uint32_t af[FM][4];
#pragma unroll
            for (int fm = 0; fm < FM; fm++){
                const int row = mbase + fm*16 + rowA_l;
                const int kb  = ks*2 + kbA_l;
                ldm_x4(sA + row*128 + ((kb ^ (row & 7)) << 4),
                       af[fm][0], af[fm][1], af[fm][2], af[fm][3]);
            }
            uint32_t bf[2][4];
#pragma unroll
            for (int fn = 0; fn < 2; fn++){
                const int row = wn*32 + fn*16 + rowB_l;
                const int kb  = ks*2 + kbB_l;
                ldm_x4(sB + row*128 + ((kb ^ (row & 7)) << 4),
                       bf[fn][0], bf[fn][1], bf[fn][2], bf[fn][3]);
            }
#pragma unroll
            for (int fm = 0; fm < FM; fm++)
#pragma unroll
                for (int j = 0; j < 4; j++)
                    mma_bf16(acc[fm][j], af[fm][0], af[fm][1], af[fm][2], af[fm][3],
                             bf[j>>1][(j&1)*2], bf[j>>1][(j&1)*2 + 1]);
        }
        __syncthreads();
        if (c + 2 < NCHUNK) issue(c + 2, c & 1);
    }

    const int r_l = lane >> 2, c_l = (lane & 3) * 2;
#pragma unroll
    for (int fm = 0; fm < FM; fm++){
#pragma unroll
        for (int j = 0; j < 4; j++){
            const int row = m0 + mbase + fm*16 + r_l;
            const int col = n0 + wn*32 + (j>>1)*16 + (j&1)*8 + c_l;
            const float* a = acc[fm][j];
            float b0 = 0.f, b1 = 0.f;
            if (BIAS){ b0 = bias[col]; b1 = bias[col+1]; }
            if (OUT_BF16){
                __nv_bfloat16* O = (__nv_bfloat16*)Cout;
                *(__nv_bfloat162*)(O + (size_t)row*ldc + col) =
                    __floats2bfloat162_rn((a[0]+b0)*alpha, (a[1]+b1)*alpha);
                *(__nv_bfloat162*)(O + (size_t)(row+8)*ldc + col) =
                    __floats2bfloat162_rn((a[2]+b0)*alpha, (a[3]+b1)*alpha);
            } else {
                float* O = (float*)Cout;
                *(float2*)(O + (size_t)row*ldc + col) = make_float2((a[0]+b0)*alpha, (a[1]+b1)*alpha);
                *(float2*)(O + (size_t)(row+8)*ldc + col) = make_float2((a[2]+b0)*alpha, (a[3]+b1)*alpha);
            }
        }
    }
}

// gemm1: z=0: CQ = dec@WfcQ^T + bfcQ ; z=1: K = enc@Wk^T + bk.  grid (8,16,2)
__global__ void __launch_bounds__(256) k_gemm1(const float* __restrict__ bfcQ,
                                               const float* __restrict__ bk){
    if (blockIdx.z == 0)
        hgemm_nt<8,64,true,true>(g_decB, g_WfcQB, g_CQB, 512, bfcQ, 1.0f,
                                 blockIdx.y*128, blockIdx.x*64);
    else
        hgemm_nt<8,64,true,true>(g_encB, g_WkB, g_QKB + (size_t)ROWS*D, 512, bk, 1.0f,
                                 blockIdx.y*128, blockIdx.x*64);
}

// gemm2: Q' = (CQ@Wq^T + bq)/8.  grid (8,16)
__global__ void __launch_bounds__(256) k_gemm2(const float* __restrict__ bq){
    hgemm_nt<8,64,true,true>(g_CQB, g_WqB, g_QKB, 512, bq, 0.125f,
                             blockIdx.y*128, blockIdx.x*64);
}

// scores: 128x128 tiles, grid (4,4,32)
__global__ void __launch_bounds__(256) k_scores_h(){
    const int z = blockIdx.z, b = z >> 3, h = z & 7;
    hgemm_nt<1,128,true,false>(g_QKB + (size_t)(b*TQ)*D + h*DH,
                               g_QKB + (size_t)(ROWS + b*TS)*D + h*DH,
                               g_scoresB + (size_t)z*TQ*TS, TS, nullptr, 1.0f,
                               blockIdx.y*128, blockIdx.x*128);
}

// ---------------- prep kernel: grouping + fp32->bf16 conversions ----------------
// blocks [0,4): grouping ; [4, 4+2816): conversions (dec, enc, Wk, Wq, WfcQ)
#define PREP_GRP_END 4
#define PREP_TOTAL   (PREP_GRP_END + 2816)

__global__ void k_prep(const int* __restrict__ src,
                       const float* __restrict__ dec, const float* __restrict__ enc,
                       const float* __restrict__ Wk, const float* __restrict__ Wq,
                       const float* __restrict__ WfcQ){
    const int blk = blockIdx.x, t = threadIdx.x;
    const int lane = t & 31, w = t >> 5;

    if (blk < PREP_GRP_END){
        __shared__ __align__(16) int shraw[4656];
        const int b = blk;
        int* stok   = shraw;            // 512
        int* sfirst = shraw + 512;      // 512
        int* sgarr  = shraw + 1024;     // 512
        int* hkey   = shraw + 1536;     // 1024
        int* hval   = shraw + 2560;     // 1024
        unsigned* sbmp = (unsigned*)(shraw + 3584); // 1000
        int* swcnt  = shraw + 4584;     // 16
        int* swbase = shraw + 4600;     // 16

        stok[t]     = src[b*TS + t];
        stok[t+256] = src[b*TS + t + 256];
        for (int i = t; i < 1024; i += 256){ hkey[i] = -1; hval[i] = 0x7fffffff; }
        for (int i = t; i < NBMPW; i += 256) sbmp[i] = 0u;
        __syncthreads();

#pragma unroll
        for (int half = 0; half < 2; half++){
            const int jj = t + half*256;
            const int tok = stok[jj];
            int slot = (int)(((unsigned)tok * 2654435761u) >> 22);
            while (true){
                int k = atomicCAS(&hkey[slot], -1, tok);
                if (k == -1 || k == tok) break;
                slot = (slot + 1) & 1023;
            }
            atomicMin(&hval[slot], jj);
            sfirst[jj] = slot;
        }
        __syncthreads();
        const int f0 = hval[sfirst[t]];
        const int f1 = hval[sfirst[t+256]];
        sfirst[t] = f0; sfirst[t+256] = f1;

        const unsigned ltm = (1u << lane) - 1u;
        const unsigned m0 = __ballot_sync(0xFFFFFFFFu, f0 == t);
        const unsigned m1 = __ballot_sync(0xFFFFFFFFu, f1 == t + 256);
        if (lane == 0){ swcnt[w] = __popc(m0); swcnt[8 + w] = __popc(m1); }
        __syncthreads();
        if (t == 0){
            int run = 0;
#pragma unroll
            for (int i = 0; i < 16; i++){ swbase[i] = run; run += swcnt[i]; }
            g_ng[b] = run;
        }
        __syncthreads();
        sgarr[t]       = swbase[w]     + __popc(m0 & ltm);
        sgarr[t + 256] = swbase[8 + w] + __popc(m1 & ltm);
        __syncthreads();

#pragma unroll
        for (int half = 0; half < 2; half++){
            const int jj = t + half*256;
            const int f = sfirst[jj];
            const int g = sgarr[f];
            g_gid[b*TS + jj] = g;
            if (f == jj){
                const int tok = stok[jj];
                g_tokmap[b*VOCABSZ + tok] = g;
                atomicOr(&sbmp[tok >> 5], 1u << (tok & 31));
            }
        }
        __syncthreads();
        for (int i = t; i < NBMPW; i += 256) g_bmp[b*NBMPW + i] = sbmp[i];
    } else {
        // conversions: dec[1M] | enc[1M] | Wk[256K] | Wq[256K] | WfcQ[256K]
        const int n1 = ROWS*D;            // 1048576
        const int nw = D*D;               // 262144
        const int i4 = ((blk - PREP_GRP_END)*256 + t) * 4;
        const float* s; __nv_bfloat16* d;
        if (i4 < n1){ s = dec + i4; d = g_decB + i4; }
        else if (i4 < 2*n1){ s = enc + (i4 - n1); d = g_encB + (i4 - n1); }
        else if (i4 < 2*n1 + nw){ s = Wk + (i4 - 2*n1); d = g_WkB + (i4 - 2*n1); }
        else if (i4 < 2*n1 + 2*nw){ s = Wq + (i4 - 2*n1 - nw); d = g_WqB + (i4 - 2*n1 - nw); }
        else { s = WfcQ + (i4 - 2*n1 - 2*nw); d = g_WfcQB + (i4 - 2*n1 - 2*nw); }
        float4 v = *(const float4*)s;
        *(__nv_bfloat162*)d       = __floats2bfloat162_rn(v.x, v.y);
        *(__nv_bfloat162*)(d + 2) = __floats2bfloat162_rn(v.z, v.w);
    }
}

// ---------------- fused attention-combine + output stream (R12 version) ----------------
// grid 2048 (b,q), 512 threads = 16 warps.
__global__ void __launch_bounds__(512) k_attn_final(
    const float* __restrict__ dec, const float* __restrict__ Wfcw,
    const float* __restrict__ bfcw, const float* __restrict__ p1,
    float* __restrict__ out){
    const int bq = blockIdx.x, b = bq >> 9, q = bq & 511;
    const int t = threadIdx.x, lane = t & 31, w = t >> 5;
    __shared__ float sattn[HEADS][512];
    __shared__ float gsum[512];
    __shared__ float sinv[HEADS];
    __shared__ float sredg[8];
    __shared__ float sredz[16];
    __shared__ unsigned sbmp[NBMPW];
    gsum[t] = 0.f;

    if (w < 8){
        const int h = w;
        const uint2* rp = (const uint2*)(g_scoresB + ((size_t)(b*HEADS + h)*TQ + q) * TS);
        float4 ev[4];
        float m = -1e30f;
#pragma unroll
        for (int j = 0; j < 4; j++){
            const uint2 u = rp[lane + 32*j];
            const __nv_bfloat162 p0 = *(const __nv_bfloat162*)&u.x;
            const __nv_bfloat162 pq = *(const __nv_bfloat162*)&u.y;
            float4 v = make_float4(__bfloat162float(p0.x), __bfloat162float(p0.y),
                                   __bfloat162float(pq.x), __bfloat162float(pq.y));
            ev[j] = v;
            m = fmaxf(m, fmaxf(fmaxf(v.x, v.y), fmaxf(v.z, v.w)));
        }
#pragma unroll
        for (int o = 16; o > 0; o >>= 1) m = fmaxf(m, __shfl_xor_sync(0xFFFFFFFFu, m, o));
        float s = 0.f;
#pragma unroll
        for (int j = 0; j < 4; j++){
            ev[j].x = __expf(ev[j].x - m); ev[j].y = __expf(ev[j].y - m);
            ev[j].z = __expf(ev[j].z - m); ev[j].w = __expf(ev[j].w - m);
            s += ev[j].x + ev[j].y + ev[j].z + ev[j].w;
        }
#pragma unroll
        for (int o = 16; o > 0; o >>= 1) s += __shfl_xor_sync(0xFFFFFFFFu, s, o);
        if (lane == 0) sinv[h] = 1.0f / (8.0f * s);
#pragma unroll
        for (int j = 0; j < 4; j++)
            *(float4*)&sattn[h][(lane + 32*j)*4] = ev[j];
    } else {
        const int t2 = t - 256;
        for (int i = t2; i < NBMPW; i += 256) sbmp[i] = g_bmp[b*NBMPW + i];
        const float* drow = dec + (size_t)bq * D;
        float pw = drow[t2]*Wfcw[t2] + drow[t2+256]*Wfcw[t2+256];
#pragma unroll
        for (int o = 16; o > 0; o >>= 1) pw += __shfl_xor_sync(0xFFFFFFFFu, pw, o);
        if (lane == 0) sredg[w - 8] = pw;
    }
    __syncthreads();

    {
        float a = 0.f;
#pragma unroll
        for (int hh = 0; hh < HEADS; hh++) a += sattn[hh][t] * sinv[hh];
        atomicAdd(&gsum[g_gid[b*TS + t]], a);
    }
    __syncthreads();

    float wsum = sredg[0];
#pragma unroll
    for (int i = 1; i < 8; i++) wsum += sredg[i];
    const float wgate = 1.0f / (1.0f + __expf(-(wsum + bfcw[0])));

    const int G = g_ng[b];
    float pz = 0.f;
    if (t < G){ float e = __expf(gsum[t]); gsum[t] = e; pz += e; }
#pragma unroll
    for (int o = 16; o > 0; o >>= 1) pz += __shfl_xor_sync(0xFFFFFFFFu, pz, o);
    if (lane == 0) sredz[w] = pz;
    __syncthreads();
    float zs = sredz[0];
#pragma unroll
    for (int i = 1; i < 16; i++) zs += sredz[i];
    const float Z = (float)(VOCABSZ - G) + zs;
    const float wz = wgate / Z;
    const float cw = 1.0f - wgate;

    const float4* p14 = (const float4*)(p1 + (size_t)bq * VOCABSZ);
    float4* o4 = (float4*)(out + (size_t)bq * VOCABSZ);
    const int* tmap = g_tokmap + (size_t)b * VOCABSZ;

#pragma unroll 4
    for (int i = t; i < VOCABSZ/4; i += 512){
        float4 v = __ldcs(&p14[i]);
        unsigned bits = (sbmp[i >> 3] >> ((i & 7) * 4)) & 0xFu;
        float4 r;
        r.x = fmaf(cw, v.x, wz); r.y = fmaf(cw, v.y, wz);
        r.z = fmaf(cw, v.z, wz); r.w = fmaf(cw, v.w, wz);
        if (bits){
            const int v0 = i * 4;
            if (bits & 1u) r.x = wz * gsum[tmap[v0+0]] + cw*v.x;
            if (bits & 2u) r.y = wz * gsum[tmap[v0+1]] + cw*v.y;
            if (bits & 4u) r.z = wz * gsum[tmap[v0+2]] + cw*v.z;
            if (bits & 8u) r.w = wz * gsum[tmap[v0+3]] + cw*v.w;
        }
        __stcs(&o4[i], r);
    }
}

// ---------------- launch ----------------
extern "C" void kernel_launch(void* const* d_in, const int* in_sizes, int n_in,
                              void* d_out, int out_size){
    int off = (in_sizes[0] == 1) ? 1 : 0;
    const float* dec  = (const float*)d_in[off + 0];
    const float* enc  = (const float*)d_in[off + 1];
    const int*   src  = (const int*)  d_in[off + 2];
    const float* p1   = (const float*)d_in[off + 3];
    const float* WfcQ = (const float*)d_in[off + 4];
    const float* bfcQ = (const float*)d_in[off + 5];
    const float* Wq   = (const float*)d_in[off + 6];
    const float* bq   = (const float*)d_in[off + 7];
    const float* Wk   = (const float*)d_in[off + 8];
    const float* bk   = (const float*)d_in[off + 9];
    const float* Wfcw = (const float*)d_in[off + 10];
    const float* bfcw = (const float*)d_in[off + 11];
    float* out = (float*)d_out;

    k_prep      <<<PREP_TOTAL, 256>>>(src, dec, enc, Wk, Wq, WfcQ);
    k_gemm1     <<<dim3(8,16,2), 256>>>(bfcQ, bk);
    k_gemm2     <<<dim3(8,16), 256>>>(bq);
    k_scores_h  <<<dim3(4,4,32), 256>>>();
    k_attn_final<<<ROWS, 512>>>(dec, Wfcw, bfcw, p1, out);
}

// round 17
// speedup vs baseline: 1.1108x; 1.0159x over previous
#include <cuda_runtime.h>
#include <cuda_bf16.h>
#include <cstdint>

#define D       512
#define HEADS   8
#define DH      64
#define NB      4
#define TQ      512
#define TS      512
#define VOCABSZ 32000
#define ROWS    (NB*TQ)          // 2048
#define NBMPW   (VOCABSZ/32)     // 1000 bitmap words per batch

// ---------------- scratch ----------------
__device__ __nv_bfloat16 g_WkB[D*D];
__device__ __nv_bfloat16 g_WqB[D*D];
__device__ __nv_bfloat16 g_WfcQB[D*D];
__device__ __nv_bfloat16 g_decB[ROWS*D];
__device__ __nv_bfloat16 g_encB[ROWS*D];
__device__ __nv_bfloat16 g_CQB[ROWS*D];             // copy-query intermediate
__device__ __nv_bfloat16 g_QKB[2*ROWS*D];           // Q' rows [0,2048), K rows [2048,4096)
__device__ __nv_bfloat16 g_scoresB[NB*HEADS*TQ*TS]; // 16.8 MB
__device__ int   g_gid[NB*TS];
__device__ int   g_ng[NB];
__device__ int   g_tokmap[NB*VOCABSZ];
__device__ unsigned g_bmp[NB*NBMPW];

// ---------------- HMMA / cp.async helpers ----------------
__device__ __forceinline__ uint32_t smem_u32(const void* p){
    uint32_t a;
    asm("{ .reg .u64 t; cvta.to.shared.u64 t, %1; cvt.u32.u64 %0, t; }" : "=r"(a) : "l"(p));
    return a;
}
__device__ __forceinline__ void ldm_x4(uint32_t addr, uint32_t& r0, uint32_t& r1,
                                       uint32_t& r2, uint32_t& r3){
    asm volatile("ldmatrix.sync.aligned.m8n8.x4.shared.b16 {%0,%1,%2,%3}, [%4];"
        : "=r"(r0), "=r"(r1), "=r"(r2), "=r"(r3) : "r"(addr));
}
__device__ __forceinline__ void mma_bf16(float* c, uint32_t a0, uint32_t a1, uint32_t a2,
                                         uint32_t a3, uint32_t b0, uint32_t b1){
    asm volatile("mma.sync.aligned.m16n8k16.row.col.f32.bf16.bf16.f32 "
        "{%0,%1,%2,%3}, {%4,%5,%6,%7}, {%8,%9}, {%0,%1,%2,%3};"
        : "+f"(c[0]), "+f"(c[1]), "+f"(c[2]), "+f"(c[3])
        : "r"(a0), "r"(a1), "r"(a2), "r"(a3), "r"(b0), "r"(b1));
}
__device__ __forceinline__ void cp16(uint32_t dst, const void* src){
    asm volatile("cp.async.cg.shared.global [%0], [%1], 16;" :: "r"(dst), "l"(src));
}
#define CP_COMMIT() asm volatile("cp.async.commit_group;" ::: "memory")
#define CP_WAIT(n)  asm volatile("cp.async.wait_group %0;" :: "n"(n) : "memory")

// ---- 128xBN-tile NT GEMM on HMMA (bf16 A+B), cp.async pipelined ----
// BN in {128, 64}. 256 threads. K = NCHUNK*64. Single smem buffer when NCHUNK==1.
template<int NCHUNK, int BN, bool OUT_BF16, bool BIAS>
__device__ __forceinline__ void hgemm_nt(
    const __nv_bfloat16* __restrict__ A, const __nv_bfloat16* __restrict__ B,
    void* __restrict__ Cout, int ldc, const float* __restrict__ bias,
    float alpha, int m0, int n0)
{
    constexpr int ABYTES = 128*128;
    constexpr int BBYTES = BN*128;
    constexpr int BUF = ABYTES + BBYTES;
    constexpr int NBUFS = (NCHUNK > 1) ? 2 : 1;
    constexpr int FM = (BN == 128) ? 4 : 2;
    constexpr int WN = (BN == 128) ? 4 : 2;

    __shared__ __align__(16) uint8_t sm[NBUFS*BUF];
    const int tid = threadIdx.x;
    const int w = tid >> 5, lane = tid & 31;
    const int wm = w / WN, wn = w % WN;
    const int mbase = wm * (FM*16);
    const uint32_t sbase = smem_u32(sm);

    float acc[FM][4][4];
#pragma unroll
    for (int i=0;i<FM;i++)
#pragma unroll
        for (int j=0;j<4;j++)
#pragma unroll
            for (int k=0;k<4;k++) acc[i][j][k] = 0.f;

    auto issue = [&](int c, int bsel){
        const uint32_t dstA = sbase + bsel*BUF;
        const uint32_t dstB = dstA + ABYTES;
#pragma unroll
        for (int it = 0; it < 4; it++){
            const int i = tid + it*256;
            const int r = i >> 3, cb = i & 7;
            const int sw = (cb ^ (r & 7)) << 4;
            cp16(dstA + r*128 + sw, A + (size_t)(m0 + r)*512 + c*64 + cb*8);
        }
#pragma unroll
        for (int it = 0; it < BN/32; it++){
            const int i = tid + it*256;
            const int r = i >> 3, cb = i & 7;
            const int sw = (cb ^ (r & 7)) << 4;
            cp16(dstB + r*128 + sw, B + (size_t)(n0 + r)*512 + c*64 + cb*8);
        }
        CP_COMMIT();
    };

    issue(0, 0);
    if (NCHUNK > 1) issue(1, 1);

    const int rowA_l = (lane & 7) + ((lane >> 3) & 1) * 8;
    const int kbA_l  = lane >> 4;
    const int rowB_l = (lane & 7) + ((lane >> 4) & 1) * 8;
    const int kbB_l  = (lane >> 3) & 1;

#pragma unroll
    for (int c = 0; c < NCHUNK; c++){
        if (c + 1 < NCHUNK) { CP_WAIT(1); } else { CP_WAIT(0); }
        __syncthreads();
        const uint32_t sA = sbase + (c & (NBUFS-1))*BUF;
        const uint32_t sB = sA + ABYTES;
#pragma unroll
        for (int ks = 0; ks < 4; ks++){
            uint32_t af[FM][4];
#pragma unroll
            for (int fm = 0; fm < FM; fm++){
                const int row = mbase + fm*16 + rowA_l;
                const int kb  = ks*2 + kbA_l;
                ldm_x4(sA + row*128 + ((kb ^ (row & 7)) << 4),
                       af[fm][0], af[fm][1], af[fm][2], af[fm][3]);
            }
            uint32_t bf[2][4];
#pragma unroll
            for (int fn = 0; fn < 2; fn++){
                const int row = wn*32 + fn*16 + rowB_l;
                const int kb  = ks*2 + kbB_l;
                ldm_x4(sB + row*128 + ((kb ^ (row & 7)) << 4),
                       bf[fn][0], bf[fn][1], bf[fn][2], bf[fn][3]);
            }
#pragma unroll
            for (int fm = 0; fm < FM; fm++)
#pragma unroll
                for (int j = 0; j < 4; j++)
                    mma_bf16(acc[fm][j], af[fm][0], af[fm][1], af[fm][2], af[fm][3],
                             bf[j>>1][(j&1)*2], bf[j>>1][(j&1)*2 + 1]);
        }
        __syncthreads();
        if (c + 2 < NCHUNK) issue(c + 2, c & 1);
    }

    const int r_l = lane >> 2, c_l = (lane & 3) * 2;
#pragma unroll
    for (int fm = 0; fm < FM; fm++){
#pragma unroll
        for (int j = 0; j < 4; j++){
            const int row = m0 + mbase + fm*16 + r_l;
            const int col = n0 + wn*32 + (j>>1)*16 + (j&1)*8 + c_l;
            const float* a = acc[fm][j];
            float b0 = 0.f, b1 = 0.f;
            if (BIAS){ b0 = bias[col]; b1 = bias[col+1]; }
            if (OUT_BF16){
                __nv_bfloat16* O = (__nv_bfloat16*)Cout;
                *(__nv_bfloat162*)(O + (size_t)row*ldc + col) =
                    __floats2bfloat162_rn((a[0]+b0)*alpha, (a[1]+b1)*alpha);
                *(__nv_bfloat162*)(O + (size_t)(row+8)*ldc + col) =
                    __floats2bfloat162_rn((a[2]+b0)*alpha, (a[3]+b1)*alpha);
            } else {
                float* O = (float*)Cout;
                *(float2*)(O + (size_t)row*ldc + col) = make_float2((a[0]+b0)*alpha, (a[1]+b1)*alpha);
                *(float2*)(O + (size_t)(row+8)*ldc + col) = make_float2((a[2]+b0)*alpha, (a[3]+b1)*alpha);
            }
        }
    }
}

// gemm1: z=0: CQ = dec@WfcQ^T + bfcQ ; z=1: K = enc@Wk^T + bk.  grid (8,16,2)
__global__ void __launch_bounds__(256) k_gemm1(const float* __restrict__ bfcQ,
                                               const float* __restrict__ bk){
    if (blockIdx.z == 0)
        hgemm_nt<8,64,true,true>(g_decB, g_WfcQB, g_CQB, 512, bfcQ, 1.0f,
                                 blockIdx.y*128, blockIdx.x*64);
    else
        hgemm_nt<8,64,true,true>(g_encB, g_WkB, g_QKB + (size_t)ROWS*D, 512, bk, 1.0f,
                                 blockIdx.y*128, blockIdx.x*64);
}

// gemm2: Q' = (CQ@Wq^T + bq)/8.  grid (8,16)
__global__ void __launch_bounds__(256) k_gemm2(const float* __restrict__ bq){
    hgemm_nt<8,64,true,true>(g_CQB, g_WqB, g_QKB, 512, bq, 0.125f,
                             blockIdx.y*128, blockIdx.x*64);
}

// scores: 128x64 tiles, single smem buffer, grid (8,4,32) = 1024 blocks
__global__ void __launch_bounds__(256) k_scores_h(){
    const int z = blockIdx.z, b = z >> 3, h = z & 7;
    hgemm_nt<1,64,true,false>(g_QKB + (size_t)(b*TQ)*D + h*DH,
                              g_QKB + (size_t)(ROWS + b*TS)*D + h*DH,
                              g_scoresB + (size_t)z*TQ*TS, TS, nullptr, 1.0f,
                              blockIdx.y*128, blockIdx.x*64);
}

// ---------------- prep kernel: grouping + fp32->bf16 conversions ----------------
// blocks [0,4): grouping ; [4, 4+2816): conversions (dec, enc, Wk, Wq, WfcQ)
#define PREP_GRP_END 4
#define PREP_TOTAL   (PREP_GRP_END + 2816)

__global__ void k_prep(const int* __restrict__ src,
                       const float* __restrict__ dec, const float* __restrict__ enc,
                       const float* __restrict__ Wk, const float* __restrict__ Wq,
                       const float* __restrict__ WfcQ){
    const int blk = blockIdx.x, t = threadIdx.x;
    const int lane = t & 31, w = t >> 5;

    if (blk < PREP_GRP_END){
        __shared__ __align__(16) int shraw[4656];
        const int b = blk;
        int* stok   = shraw;            // 512
        int* sfirst = shraw + 512;      // 512
        int* sgarr  = shraw + 1024;     // 512
        int* hkey   = shraw + 1536;     // 1024
        int* hval   = shraw + 2560;     // 1024
        unsigned* sbmp = (unsigned*)(shraw + 3584); // 1000
        int* swcnt  = shraw + 4584;     // 16
        int* swbase = shraw + 4600;     // 16

        stok[t]     = src[b*TS + t];
        stok[t+256] = src[b*TS + t + 256];
        for (int i = t; i < 1024; i += 256){ hkey[i] = -1; hval[i] = 0x7fffffff; }
        for (int i = t; i < NBMPW; i += 256) sbmp[i] = 0u;
        __syncthreads();

#pragma unroll
        for (int half = 0; half < 2; half++){
            const int jj = t + half*256;
            const int tok = stok[jj];
            int slot = (int)(((unsigned)tok * 2654435761u) >> 22);
            while (true){
                int k = atomicCAS(&hkey[slot], -1, tok);
                if (k == -1 || k == tok) break;
                slot = (slot + 1) & 1023;
            }
            atomicMin(&hval[slot], jj);
            sfirst[jj] = slot;
        }
        __syncthreads();
        const int f0 = hval[sfirst[t]];
        const int f1 = hval[sfirst[t+256]];
        sfirst[t] = f0; sfirst[t+256] = f1;

        const unsigned ltm = (1u << lane) - 1u;
        const unsigned m0 = __ballot_sync(0xFFFFFFFFu, f0 == t);
        const unsigned m1 = __ballot_sync(0xFFFFFFFFu, f1 == t + 256);
        if (lane == 0){ swcnt[w] = __popc(m0); swcnt[8 + w] = __popc(m1); }
        __syncthreads();
        if (t == 0){
            int run = 0;
#pragma unroll
            for (int i = 0; i < 16; i++){ swbase[i] = run; run += swcnt[i]; }
            g_ng[b] = run;
        }
        __syncthreads();
        sgarr[t]       = swbase[w]     + __popc(m0 & ltm);
        sgarr[t + 256] = swbase[8 + w] + __popc(m1 & ltm);
        __syncthreads();

#pragma unroll
        for (int half = 0; half < 2; half++){
            const int jj = t + half*256;
            const int f = sfirst[jj];
            const int g = sgarr[f];
            g_gid[b*TS + jj] = g;
            if (f == jj){
                const int tok = stok[jj];
                g_tokmap[b*VOCABSZ + tok] = g;
                atomicOr(&sbmp[tok >> 5], 1u << (tok & 31));
            }
        }
        __syncthreads();
        for (int i = t; i < NBMPW; i += 256) g_bmp[b*NBMPW + i] = sbmp[i];
    } else {
        // conversions: dec[1M] | enc[1M] | Wk[256K] | Wq[256K] | WfcQ[256K]
        const int n1 = ROWS*D;            // 1048576
        const int nw = D*D;               // 262144
        const int i4 = ((blk - PREP_GRP_END)*256 + t) * 4;
        const float* s; __nv_bfloat16* d;
        if (i4 < n1){ s = dec + i4; d = g_decB + i4; }
        else if (i4 < 2*n1){ s = enc + (i4 - n1); d = g_encB + (i4 - n1); }
        else if (i4 < 2*n1 + nw){ s = Wk + (i4 - 2*n1); d = g_WkB + (i4 - 2*n1); }
        else if (i4 < 2*n1 + 2*nw){ s = Wq + (i4 - 2*n1 - nw); d = g_WqB + (i4 - 2*n1 - nw); }
        else { s = WfcQ + (i4 - 2*n1 - 2*nw); d = g_WfcQB + (i4 - 2*n1 - 2*nw); }
        float4 v = *(const float4*)s;
        *(__nv_bfloat162*)d       = __floats2bfloat162_rn(v.x, v.y);
        *(__nv_bfloat162*)(d + 2) = __floats2bfloat162_rn(v.z, v.w);
    }
}

// ---------------- fused attention-combine + output stream ----------------
// grid 2048 (b,q), 512 threads = 16 warps.
__global__ void __launch_bounds__(512) k_attn_final(
    const float* __restrict__ dec, const float* __restrict__ Wfcw,
    const float* __restrict__ bfcw, const float* __restrict__ p1,
    float* __restrict__ out){
    const int bq = blockIdx.x, b = bq >> 9, q = bq & 511;
    const int t = threadIdx.x, lane = t & 31, w = t >> 5;
    __shared__ float sattn[HEADS][512];
    __shared__ float gsum[512];
    __shared__ float sinv[HEADS];
    __shared__ float sredg[8];
    __shared__ float sredz[16];
    __shared__ unsigned sbmp[NBMPW];
    gsum[t] = 0.f;

    if (w < 8){
        const int h = w;
        const uint2* rp = (const uint2*)(g_scoresB + ((size_t)(b*HEADS + h)*TQ + q) * TS);
        float4 ev[4];
        float m = -1e30f;
#pragma unroll
        for (int j = 0; j < 4; j++){
            const uint2 u = rp[lane + 32*j];
            const __nv_bfloat162 p0 = *(const __nv_bfloat162*)&u.x;
            const __nv_bfloat162 pq = *(const __nv_bfloat162*)&u.y;
            float4 v = make_float4(__bfloat162float(p0.x), __bfloat162float(p0.y),
                                   __bfloat162float(pq.x), __bfloat162float(pq.y));
            ev[j] = v;
            m = fmaxf(m, fmaxf(fmaxf(v.x, v.y), fmaxf(v.z, v.w)));
        }
#pragma unroll
        for (int o = 16; o > 0; o >>= 1) m = fmaxf(m, __shfl_xor_sync(0xFFFFFFFFu, m, o));
        float s = 0.f;
#pragma unroll
        for (int j = 0; j < 4; j++){
            ev[j].x = __expf(ev[j].x - m); ev[j].y = __expf(ev[j].y - m);
            ev[j].z = __expf(ev[j].z - m); ev[j].w = __expf(ev[j].w - m);
            s += ev[j].x + ev[j].y + ev[j].z + ev[j].w;
        }
#pragma unroll
        for (int o = 16; o > 0; o >>= 1) s += __shfl_xor_sync(0xFFFFFFFFu, s, o);
        if (lane == 0) sinv[h] = 1.0f / (8.0f * s);
#pragma unroll
        for (int j = 0; j < 4; j++)
            *(float4*)&sattn[h][(lane + 32*j)*4] = ev[j];
    } else {
        const int t2 = t - 256;
        for (int i = t2; i < NBMPW; i += 256) sbmp[i] = g_bmp[b*NBMPW + i];
        const float* drow = dec + (size_t)bq * D;
        float pw = drow[t2]*Wfcw[t2] + drow[t2+256]*Wfcw[t2+256];
#pragma unroll
        for (int o = 16; o > 0; o >>= 1) pw += __shfl_xor_sync(0xFFFFFFFFu, pw, o);
        if (lane == 0) sredg[w - 8] = pw;
    }
    __syncthreads();

    {
        float a = 0.f;
#pragma unroll
        for (int hh = 0; hh < HEADS; hh++) a += sattn[hh][t] * sinv[hh];
        atomicAdd(&gsum[g_gid[b*TS + t]], a);
    }
    __syncthreads();

    float wsum = sredg[0];
#pragma unroll
    for (int i = 1; i < 8; i++) wsum += sredg[i];
    const float wgate = 1.0f / (1.0f + __expf(-(wsum + bfcw[0])));

    const int G = g_ng[b];
    float pz = 0.f;
    if (t < G){ float e = __expf(gsum[t]); gsum[t] = e; pz += e; }
#pragma unroll
    for (int o = 16; o > 0; o >>= 1) pz += __shfl_xor_sync(0xFFFFFFFFu, pz, o);
    if (lane == 0) sredz[w] = pz;
    __syncthreads();
    float zs = sredz[0];
#pragma unroll
    for (int i = 1; i < 16; i++) zs += sredz[i];
    const float Z = (float)(VOCABSZ - G) + zs;
    const float wz = wgate / Z;
    const float cw = 1.0f - wgate;

    const float4* p14 = (const float4*)(p1 + (size_t)bq * VOCABSZ);
    float4* o4 = (float4*)(out + (size_t)bq * VOCABSZ);
    const int* tmap = g_tokmap + (size_t)b * VOCABSZ;

#pragma unroll 4
    for (int i = t; i < VOCABSZ/4; i += 512){
        float4 v = __ldcs(&p14[i]);
        unsigned bits = (sbmp[i >> 3] >> ((i & 7) * 4)) & 0xFu;
        float4 r;
        r.x = fmaf(cw, v.x, wz); r.y = fmaf(cw, v.y, wz);
        r.z = fmaf(cw, v.z, wz); r.w = fmaf(cw, v.w, wz);
        if (bits){
            const int v0 = i * 4;
            if (bits & 1u) r.x = wz * gsum[tmap[v0+0]] + cw*v.x;
            if (bits & 2u) r.y = wz * gsum[tmap[v0+1]] + cw*v.y;
            if (bits & 4u) r.z = wz * gsum[tmap[v0+2]] + cw*v.z;
            if (bits & 8u) r.w = wz * gsum[tmap[v0+3]] + cw*v.w;
        }
        __stcs(&o4[i], r);
    }
}

// ---------------- launch ----------------
extern "C" void kernel_launch(void* const* d_in, const int* in_sizes, int n_in,
                              void* d_out, int out_size){
    int off = (in_sizes[0] == 1) ? 1 : 0;
    const float* dec  = (const float*)d_in[off + 0];
    const float* enc  = (const float*)d_in[off + 1];
    const int*   src  = (const int*)  d_in[off + 2];
    const float* p1   = (const float*)d_in[off + 3];
    const float* WfcQ = (const float*)d_in[off + 4];
    const float* bfcQ = (const float*)d_in[off + 5];
    const float* Wq   = (const float*)d_in[off + 6];
    const float* bq   = (const float*)d_in[off + 7];
    const float* Wk   = (const float*)d_in[off + 8];
    const float* bk   = (const float*)d_in[off + 9];
    const float* Wfcw = (const float*)d_in[off + 10];
    const float* bfcw = (const float*)d_in[off + 11];
    float* out = (float*)d_out;

    k_prep      <<<PREP_TOTAL, 256>>>(src, dec, enc, Wk, Wq, WfcQ);
    k_gemm1     <<<dim3(8,16,2), 256>>>(bfcQ, bk);
    k_gemm2     <<<dim3(8,16), 256>>>(bq);
    k_scores_h  <<<dim3(8,4,32), 256>>>();
    k_attn_final<<<ROWS, 512>>>(dec, Wfcw, bfcw, p1, out);
}